// round 15
// baseline (speedup 1.0000x reference)
#include <cuda_runtime.h>
#include <math.h>
#include <cstdint>

// Problem constants (fixed by reference: B=32, T=8192, K=16)
#define BT_ROWS   (32 * 8192)
#define KDIM      16
#define ELEMS     (BT_ROWS * KDIM)       // 4194304
#define NTHR      512
#define TILE      512                    // elements per stage
#define NTILES    (ELEMS / TILE)         // 8192
#define NBLK      456                    // 152 SMs x 3 CTAs -> single wave
#define NSTAGE    3
#define EPS_F     1e-7f
#define FULLMASK  0xffffffffu

// ---- Stage layout in shared memory (bytes), TILE=512; everything staged ----
#define OFF_CID    0                     // 2 KB each
#define OFF_OCID   2048
#define OFF_TRIG   4096
#define OFF_VLD    6144
#define OFF_OFIRE  8192
#define OFF_OVLD   10240
#define OFF_OCAN   12288
#define OFF_CLOG   14336                 // 6 KB
#define OFF_LIVE   20480                 // up to 2 KB
#define OFF_WSC    22528                 // 128 B (32 rows)
#define OFF_OSW    22656                 // 128 B
#define STAGE_BYTES 22784
#define SMEM_TOTAL  (NSTAGE * STAGE_BYTES)   // 68352 -> 3 CTAs/SM

// Per-block partial sums: [6][NBLK]
__device__ float g_part[6 * NBLK];
__device__ unsigned int g_sem;

__device__ __forceinline__ float warp_sum_f(float v) {
#pragma unroll
    for (int o = 16; o > 0; o >>= 1) v += __shfl_down_sync(FULLMASK, v, o);
    return v;
}
__device__ __forceinline__ double warp_sum_d(double v) {
#pragma unroll
    for (int o = 16; o > 0; o >>= 1) v += __shfl_down_sync(FULLMASK, v, o);
    return v;
}

// ---- TMA 1D bulk copy + mbarrier helpers ----
__device__ __forceinline__ void tma_bulk(uint32_t dst, const void* src,
                                         uint32_t size, uint32_t mbar) {
    asm volatile(
        "cp.async.bulk.shared::cta.global.mbarrier::complete_tx::bytes "
        "[%0], [%1], %2, [%3];"
        :: "r"(dst), "l"(src), "r"(size), "r"(mbar) : "memory");
}
__device__ __forceinline__ void mbar_init(uint32_t mbar, uint32_t count) {
    asm volatile("mbarrier.init.shared.b64 [%0], %1;" :: "r"(mbar), "r"(count) : "memory");
}
__device__ __forceinline__ void mbar_expect_tx(uint32_t mbar, uint32_t bytes) {
    asm volatile("mbarrier.arrive.expect_tx.shared.b64 _, [%0], %1;"
                 :: "r"(mbar), "r"(bytes) : "memory");
}
__device__ __forceinline__ void mbar_arrive(uint32_t mbar) {
    asm volatile("mbarrier.arrive.release.cta.shared::cta.b64 _, [%0];"
                 :: "r"(mbar) : "memory");
}
__device__ __forceinline__ void mbar_wait(uint32_t mbar, uint32_t parity) {
    asm volatile(
        "{\n\t"
        ".reg .pred P;\n\t"
        "LAB_WAIT_%=:\n\t"
        "mbarrier.try_wait.parity.acquire.cta.shared::cta.b64 P, [%0], %1, 0x989680;\n\t"
        "@P bra LAB_DONE_%=;\n\t"
        "bra LAB_WAIT_%=;\n\t"
        "LAB_DONE_%=:\n\t"
        "}"
        :: "r"(mbar), "r"(parity) : "memory");
}

__global__ __launch_bounds__(NTHR, 3)
void lifecycle_fused(const float* __restrict__ trig,
                     const float* __restrict__ vld,
                     const float* __restrict__ clog,
                     const float* __restrict__ wsc,
                     const void*  __restrict__ live_raw,
                     const int*   __restrict__ cid,
                     const float* __restrict__ ofire,
                     const int*   __restrict__ ocan,
                     const float* __restrict__ ovld,
                     const float* __restrict__ osw,
                     const int*   __restrict__ ocid,
                     float* __restrict__ out)
{
    extern __shared__ char smem[];
    __shared__ __align__(8) unsigned long long s_full[NSTAGE];
    __shared__ __align__(8) unsigned long long s_empty[NSTAGE];

    // ---- live_mask dtype sniff (same 64 words for every block; L2 broadcast) ----
    __shared__ unsigned int s_or, s_f32;
    __shared__ int s_mode;
    if (threadIdx.x == 0) { s_or = 0u; s_f32 = 0u; }
    __syncthreads();
    if (threadIdx.x < 64) {
        unsigned int x = ((const unsigned int*)live_raw)[threadIdx.x];
        unsigned int f = (x == 0x3F800000u) ? 1u : 0u;
        unsigned int a = f ? 0u : x;
#pragma unroll
        for (int o = 16; o > 0; o >>= 1) {
            a |= __shfl_down_sync(FULLMASK, a, o);
            f |= __shfl_down_sync(FULLMASK, f, o);
        }
        if ((threadIdx.x & 31) == 0) { atomicOr(&s_or, a); atomicOr(&s_f32, f); }
    }
    __syncthreads();
    if (threadIdx.x == 0) s_mode = s_f32 ? 2 : ((s_or & ~1u) ? 0 : 1);
    __syncthreads();
    const int mode = s_mode;                    // 0=u8, 1=i32, 2=f32

    const int tid = threadIdx.x;
    const int bid = blockIdx.x;
    const int count = (NTILES - bid + NBLK - 1) / NBLK;   // tiles for this block

    const uint32_t sbase = (uint32_t)__cvta_generic_to_shared(smem);
    const uint32_t fbase = (uint32_t)__cvta_generic_to_shared(s_full);
    const uint32_t ebase = (uint32_t)__cvta_generic_to_shared(s_empty);
    const uint32_t live_sz = (mode == 0) ? 512u : 2048u;
    const uint32_t tx_bytes = 7*2048u + 6144u + live_sz + 128u + 128u;

    // ---- mbarrier init ----
    if (tid == 0) {
#pragma unroll
        for (int s = 0; s < NSTAGE; ++s) {
            mbar_init(fbase + s*8, 1);
            mbar_init(ebase + s*8, NTHR);
        }
    }
    __syncthreads();

    // ---- tile stage via TMA bulk (single thread issues 11 descriptors) ----
    auto stage_tma = [&](int j) {   // j = local tile ordinal; caller: tid==0 only
        const int t = bid + j * NBLK;
        const size_t eb = (size_t)t * TILE;
        const int s = j % NSTAGE;
        const uint32_t sb = sbase + (uint32_t)s * STAGE_BYTES;
        const uint32_t mb = fbase + (uint32_t)s * 8;
        mbar_expect_tx(mb, tx_bytes);
        tma_bulk(sb + OFF_CID,   (const char*)cid   + eb*4, 2048, mb);
        tma_bulk(sb + OFF_OCID,  (const char*)ocid  + eb*4, 2048, mb);
        tma_bulk(sb + OFF_TRIG,  (const char*)trig  + eb*4, 2048, mb);
        tma_bulk(sb + OFF_VLD,   (const char*)vld   + eb*4, 2048, mb);
        tma_bulk(sb + OFF_OFIRE, (const char*)ofire + eb*4, 2048, mb);
        tma_bulk(sb + OFF_OVLD,  (const char*)ovld  + eb*4, 2048, mb);
        tma_bulk(sb + OFF_OCAN,  (const char*)ocan  + eb*4, 2048, mb);
        tma_bulk(sb + OFF_CLOG,  (const char*)clog  + eb*12, 6144, mb);
        if (mode == 0) tma_bulk(sb + OFF_LIVE, (const char*)live_raw + eb,   512,  mb);
        else           tma_bulk(sb + OFF_LIVE, (const char*)live_raw + eb*4, 2048, mb);
        tma_bulk(sb + OFF_WSC, (const char*)wsc + (eb >> 4)*4, 128, mb);
        tma_bulk(sb + OFF_OSW, (const char*)osw + (eb >> 4)*4, 128, mb);
    };

    float fire_s = 0.f, m_s = 0.f, val_s = 0.f, can_s = 0.f, has_s = 0.f, w_s = 0.f;

    const int k   = tid & 15;   // element within row
    const int row = tid >> 4;   // local row (32 rows per tile)

    // ---- prologue: fill all 3 stages ----
    if (tid == 0) { stage_tma(0); stage_tma(1); stage_tma(2); }

#pragma unroll 1
    for (int j = 0; j < count; ++j) {
        const int s = j % NSTAGE;
        const uint32_t par = (uint32_t)((j / NSTAGE) & 1);
        mbar_wait(fbase + (uint32_t)s * 8, par);

        const char* sb = smem + s * STAGE_BYTES;

        const int   c  = ((const int*)(sb + OFF_CID))[tid];
        const float th = ((const float*)(sb + OFF_TRIG))[tid];
        const float vv = ((const float*)(sb + OFF_VLD))[tid];

        bool lm;
        if (mode == 0)      lm = ((const unsigned char*)(sb + OFF_LIVE))[tid] != 0;
        else if (mode == 1) lm = ((const int*)(sb + OFF_LIVE))[tid] != 0;
        else                lm = ((const float*)(sb + OFF_LIVE))[tid] != 0.0f;

        if (lm) {
            m_s += 1.0f;

            // 16-entry row ocid table: 4 broadcast LDS.128 (live lanes only)
            int ov[16];
            {
                const int4* orow = (const int4*)(sb + OFF_OCID) + row * 4;
#pragma unroll
                for (int gq = 0; gq < 4; ++gq) {
                    int4 tt = orow[gq];
                    ov[4*gq+0] = tt.x; ov[4*gq+1] = tt.y; ov[4*gq+2] = tt.z; ov[4*gq+3] = tt.w;
                }
            }
            // first-match scan: build match mask, ffs for smallest ko
            unsigned int mmask = 0u;
#pragma unroll
            for (int ko = 0; ko < 16; ++ko)
                mmask |= (ov[ko] == c) ? (1u << ko) : 0u;
            const bool fnd = (mmask != 0u) && (c != 0);
            const int  idx = fnd ? (__ffs(mmask) - 1) : 0;
            const int  gl  = row * 16 + idx;

            // oracle targets are exactly {0,1}; select-form BCE is exact
            const bool tfb = fnd && (((const float*)(sb + OFF_OFIRE))[gl] != 0.0f);
            const bool tvb = fnd && (((const float*)(sb + OFF_OVLD))[gl] != 0.0f);
            const int  ct  = fnd ? ((const int*)(sb + OFF_OCAN))[gl] : 0;

            float p = fminf(fmaxf(th, EPS_F), 1.0f - EPS_F);
            fire_s -= __logf(tfb ? p : 1.0f - p);

            float q = fminf(fmaxf(vv, EPS_F), 1.0f - EPS_F);
            val_s -= __logf(tvb ? q : 1.0f - q);

            if (ct > 0) {
                const float* lp = (const float*)(sb + OFF_CLOG) + (size_t)tid * 3;
                float x0 = lp[0], x1 = lp[1], x2 = lp[2];
                float mx = fmaxf(x0, fmaxf(x1, x2));
                float s2 = __expf(x0 - mx) + __expf(x1 - mx) + __expf(x2 - mx);
                int tgt = ct - 1;
                tgt = tgt < 0 ? 0 : (tgt > 2 ? 2 : tgt);
                float xt = (tgt == 0) ? x0 : ((tgt == 1) ? x1 : x2);
                can_s += mx + __logf(s2) - xt;
                has_s += 1.0f;
            }
        }

        // write-head BCE-with-logits: one per row
        if (k == 0) {
            float wx = ((const float*)(sb + OFF_WSC))[row];
            float wy = ((const float*)(sb + OFF_OSW))[row];
            w_s += fmaxf(wx, 0.0f) - wx * wy + __logf(1.0f + __expf(-fabsf(wx)));
        }

        // done reading buffer s -> arrive on its empty barrier (no block barrier!)
        mbar_arrive(ebase + (uint32_t)s * 8);

        // producer (tid 0): wait until ALL threads released buffer s, then refill
        if (tid == 0 && j + NSTAGE < count) {
            mbar_wait(ebase + (uint32_t)s * 8, par);
            stage_tma(j + NSTAGE);
        }
    }

    // ---- Deterministic block reduction of 6 float accumulators ----
    __shared__ float sm[16][6];
    __syncthreads();    // quiesce pipeline before reusing nothing; orders accumulators (regs) trivially
    {
        float vals[6] = {fire_s, m_s, val_s, can_s, has_s, w_s};
#pragma unroll
        for (int jj = 0; jj < 6; ++jj) vals[jj] = warp_sum_f(vals[jj]);
        const int wid = tid >> 5, lid = tid & 31;
        if (lid == 0) {
#pragma unroll
            for (int jj = 0; jj < 6; ++jj) sm[wid][jj] = vals[jj];
        }
        __syncthreads();
        if (wid == 0) {
#pragma unroll
            for (int jj = 0; jj < 6; ++jj) {
                float v = (lid < (NTHR / 32)) ? sm[lid][jj] : 0.0f;
                v = warp_sum_f(v);
                if (lid == 0) g_part[jj * NBLK + blockIdx.x] = v;
            }
        }
    }

    // ---- Last-block finalize ----
    __shared__ int s_last;
    if (tid == 0) {
        __threadfence();
        unsigned int t = atomicAdd(&g_sem, 1u);
        s_last = (t == NBLK - 1) ? 1 : 0;
    }
    __syncthreads();
    if (!s_last) return;

    __shared__ double smd[16];
    double tot[6];
#pragma unroll
    for (int jj = 0; jj < 6; ++jj) {
        double v = 0.0;
        for (int i = tid; i < NBLK; i += NTHR)
            v += (double)__ldcg(&g_part[jj * NBLK + i]);
        v = warp_sum_d(v);
        const int wid = tid >> 5, lid = tid & 31;
        if (lid == 0) smd[wid] = v;
        __syncthreads();
        double r = 0.0;
        if (wid == 0) {
            r = (lid < (NTHR / 32)) ? smd[lid] : 0.0;
            r = warp_sum_d(r);
        }
        tot[jj] = r;
        __syncthreads();
    }
    if (tid == 0) {
        double n     = fmax(tot[1], 1.0);
        double fire  = tot[0] / n;
        double canc  = (tot[4] > 0.0) ? tot[3] / fmax(tot[4], 1.0) : 0.0;
        double valid = 0.5 * tot[2] / n;
        double wr    = 0.5 * tot[5] / (double)BT_ROWS;
        out[0] = (float)fire;
        out[1] = (float)canc;
        out[2] = (float)valid;
        out[3] = (float)wr;
        out[4] = (float)(fire + canc + valid + wr);
        g_sem = 0;
    }
}

extern "C" void kernel_launch(void* const* d_in, const int* in_sizes, int n_in,
                              void* d_out, int out_size)
{
    (void)in_sizes; (void)n_in; (void)out_size;
    cudaFuncSetAttribute(lifecycle_fused,
                         cudaFuncAttributeMaxDynamicSharedMemorySize, SMEM_TOTAL);
    lifecycle_fused<<<NBLK, NTHR, SMEM_TOTAL>>>(
        (const float*)d_in[0],          // trigger_hazard
        (const float*)d_in[1],          // validity
        (const float*)d_in[2],          // cancel_logits
        (const float*)d_in[3],          // write_score
        d_in[4],                        // live_mask (dtype auto-detected)
        (const int*)d_in[5],            // contract_id
        (const float*)d_in[6],          // oracle_fire
        (const int*)d_in[7],            // oracle_cancel
        (const float*)d_in[8],          // oracle_valid
        (const float*)d_in[9],          // oracle_should_write
        (const int*)d_in[10],           // oracle_contract_id
        (float*)d_out);
}

// round 16
// speedup vs baseline: 1.0048x; 1.0048x over previous
#include <cuda_runtime.h>
#include <math.h>
#include <cstdint>

// Problem constants (fixed by reference: B=32, T=8192, K=16)
#define BT_ROWS   (32 * 8192)
#define KDIM      16
#define ELEMS     (BT_ROWS * KDIM)       // 4194304
#define NTHR      512
#define NWARP     (NTHR / 32)            // 16
#define TILE      512                    // elements per stage
#define NTILES    (ELEMS / TILE)         // 8192
#define NBLK      456                    // 152 SMs x 3 CTAs -> single wave
#define NSTAGE    3
#define EPS_F     1e-7f
#define FULLMASK  0xffffffffu

// ---- Stage layout in shared memory (bytes), TILE=512; everything staged ----
#define OFF_CID    0                     // 2 KB each
#define OFF_OCID   2048
#define OFF_TRIG   4096
#define OFF_VLD    6144
#define OFF_OFIRE  8192
#define OFF_OVLD   10240
#define OFF_OCAN   12288
#define OFF_CLOG   14336                 // 6 KB
#define OFF_LIVE   20480                 // up to 2 KB
#define OFF_WSC    22528                 // 128 B (32 rows)
#define OFF_OSW    22656                 // 128 B
#define STAGE_BYTES 22784
#define SMEM_TOTAL  (NSTAGE * STAGE_BYTES)   // 68352 -> 3 CTAs/SM

// Per-block partial sums: [6][NBLK]
__device__ float g_part[6 * NBLK];
__device__ unsigned int g_sem;

__device__ __forceinline__ float warp_sum_f(float v) {
#pragma unroll
    for (int o = 16; o > 0; o >>= 1) v += __shfl_down_sync(FULLMASK, v, o);
    return v;
}
__device__ __forceinline__ double warp_sum_d(double v) {
#pragma unroll
    for (int o = 16; o > 0; o >>= 1) v += __shfl_down_sync(FULLMASK, v, o);
    return v;
}

// ---- TMA 1D bulk copy + mbarrier helpers ----
__device__ __forceinline__ void tma_bulk(uint32_t dst, const void* src,
                                         uint32_t size, uint32_t mbar) {
    asm volatile(
        "cp.async.bulk.shared::cta.global.mbarrier::complete_tx::bytes "
        "[%0], [%1], %2, [%3];"
        :: "r"(dst), "l"(src), "r"(size), "r"(mbar) : "memory");
}
__device__ __forceinline__ void mbar_init(uint32_t mbar, uint32_t count) {
    asm volatile("mbarrier.init.shared.b64 [%0], %1;" :: "r"(mbar), "r"(count) : "memory");
}
__device__ __forceinline__ void mbar_expect_tx(uint32_t mbar, uint32_t bytes) {
    asm volatile("mbarrier.arrive.expect_tx.shared.b64 _, [%0], %1;"
                 :: "r"(mbar), "r"(bytes) : "memory");
}
__device__ __forceinline__ void mbar_arrive(uint32_t mbar) {
    asm volatile("mbarrier.arrive.release.cta.shared::cta.b64 _, [%0];"
                 :: "r"(mbar) : "memory");
}
__device__ __forceinline__ void mbar_wait(uint32_t mbar, uint32_t parity) {
    asm volatile(
        "{\n\t"
        ".reg .pred P;\n\t"
        "LAB_WAIT_%=:\n\t"
        "mbarrier.try_wait.parity.acquire.cta.shared::cta.b64 P, [%0], %1, 0x989680;\n\t"
        "@P bra LAB_DONE_%=;\n\t"
        "bra LAB_WAIT_%=;\n\t"
        "LAB_DONE_%=:\n\t"
        "}"
        :: "r"(mbar), "r"(parity) : "memory");
}

__global__ __launch_bounds__(NTHR, 3)
void lifecycle_fused(const float* __restrict__ trig,
                     const float* __restrict__ vld,
                     const float* __restrict__ clog,
                     const float* __restrict__ wsc,
                     const void*  __restrict__ live_raw,
                     const int*   __restrict__ cid,
                     const float* __restrict__ ofire,
                     const int*   __restrict__ ocan,
                     const float* __restrict__ ovld,
                     const float* __restrict__ osw,
                     const int*   __restrict__ ocid,
                     float* __restrict__ out)
{
    extern __shared__ char smem[];
    __shared__ __align__(8) unsigned long long s_full[NSTAGE];
    __shared__ __align__(8) unsigned long long s_empty[NSTAGE];

    // ---- live_mask dtype sniff (same 64 words for every block; L2 broadcast) ----
    __shared__ unsigned int s_or, s_f32;
    __shared__ int s_mode;
    if (threadIdx.x == 0) { s_or = 0u; s_f32 = 0u; }
    __syncthreads();
    if (threadIdx.x < 64) {
        unsigned int x = ((const unsigned int*)live_raw)[threadIdx.x];
        unsigned int f = (x == 0x3F800000u) ? 1u : 0u;
        unsigned int a = f ? 0u : x;
#pragma unroll
        for (int o = 16; o > 0; o >>= 1) {
            a |= __shfl_down_sync(FULLMASK, a, o);
            f |= __shfl_down_sync(FULLMASK, f, o);
        }
        if ((threadIdx.x & 31) == 0) { atomicOr(&s_or, a); atomicOr(&s_f32, f); }
    }
    __syncthreads();
    if (threadIdx.x == 0) s_mode = s_f32 ? 2 : ((s_or & ~1u) ? 0 : 1);
    __syncthreads();
    const int mode = s_mode;                    // 0=u8, 1=i32, 2=f32

    const int tid = threadIdx.x;
    const int bid = blockIdx.x;
    const int count = (NTILES - bid + NBLK - 1) / NBLK;   // tiles for this block

    const uint32_t sbase = (uint32_t)__cvta_generic_to_shared(smem);
    const uint32_t fbase = (uint32_t)__cvta_generic_to_shared(s_full);
    const uint32_t ebase = (uint32_t)__cvta_generic_to_shared(s_empty);
    const uint32_t live_sz = (mode == 0) ? 512u : 2048u;
    const uint32_t tx_bytes = 7*2048u + 6144u + live_sz + 128u + 128u;

    // ---- mbarrier init ----
    if (tid == 0) {
#pragma unroll
        for (int s = 0; s < NSTAGE; ++s) {
            mbar_init(fbase + s*8, 1);
            mbar_init(ebase + s*8, NWARP);   // one arrive per warp
        }
    }
    __syncthreads();

    // ---- tile stage via TMA bulk (single thread issues 11 descriptors) ----
    auto stage_tma = [&](int j) {   // j = local tile ordinal; caller: tid==0 only
        const int t = bid + j * NBLK;
        const size_t eb = (size_t)t * TILE;
        const int s = j % NSTAGE;
        const uint32_t sb = sbase + (uint32_t)s * STAGE_BYTES;
        const uint32_t mb = fbase + (uint32_t)s * 8;
        mbar_expect_tx(mb, tx_bytes);
        tma_bulk(sb + OFF_CID,   (const char*)cid   + eb*4, 2048, mb);
        tma_bulk(sb + OFF_OCID,  (const char*)ocid  + eb*4, 2048, mb);
        tma_bulk(sb + OFF_TRIG,  (const char*)trig  + eb*4, 2048, mb);
        tma_bulk(sb + OFF_VLD,   (const char*)vld   + eb*4, 2048, mb);
        tma_bulk(sb + OFF_OFIRE, (const char*)ofire + eb*4, 2048, mb);
        tma_bulk(sb + OFF_OVLD,  (const char*)ovld  + eb*4, 2048, mb);
        tma_bulk(sb + OFF_OCAN,  (const char*)ocan  + eb*4, 2048, mb);
        tma_bulk(sb + OFF_CLOG,  (const char*)clog  + eb*12, 6144, mb);
        if (mode == 0) tma_bulk(sb + OFF_LIVE, (const char*)live_raw + eb,   512,  mb);
        else           tma_bulk(sb + OFF_LIVE, (const char*)live_raw + eb*4, 2048, mb);
        tma_bulk(sb + OFF_WSC, (const char*)wsc + (eb >> 4)*4, 128, mb);
        tma_bulk(sb + OFF_OSW, (const char*)osw + (eb >> 4)*4, 128, mb);
    };

    float fire_s = 0.f, m_s = 0.f, val_s = 0.f, can_s = 0.f, has_s = 0.f, w_s = 0.f;

    const int k   = tid & 15;   // element within row
    const int row = tid >> 4;   // local row (32 rows per tile)

    // ---- prologue: fill all 3 stages ----
    if (tid == 0) { stage_tma(0); stage_tma(1); stage_tma(2); }

#pragma unroll 1
    for (int j = 0; j < count; ++j) {
        const int s = j % NSTAGE;
        const uint32_t par = (uint32_t)((j / NSTAGE) & 1);
        mbar_wait(fbase + (uint32_t)s * 8, par);

        const char* sb = smem + s * STAGE_BYTES;

        const int   c  = ((const int*)(sb + OFF_CID))[tid];
        const float th = ((const float*)(sb + OFF_TRIG))[tid];
        const float vv = ((const float*)(sb + OFF_VLD))[tid];

        bool lm;
        if (mode == 0)      lm = ((const unsigned char*)(sb + OFF_LIVE))[tid] != 0;
        else if (mode == 1) lm = ((const int*)(sb + OFF_LIVE))[tid] != 0;
        else                lm = ((const float*)(sb + OFF_LIVE))[tid] != 0.0f;

        if (lm) {
            m_s += 1.0f;

            // 16-entry row ocid table: 4 broadcast LDS.128 (live lanes only)
            int ov[16];
            {
                const int4* orow = (const int4*)(sb + OFF_OCID) + row * 4;
#pragma unroll
                for (int gq = 0; gq < 4; ++gq) {
                    int4 tt = orow[gq];
                    ov[4*gq+0] = tt.x; ov[4*gq+1] = tt.y; ov[4*gq+2] = tt.z; ov[4*gq+3] = tt.w;
                }
            }
            // first-match scan: build match mask, ffs for smallest ko
            unsigned int mmask = 0u;
#pragma unroll
            for (int ko = 0; ko < 16; ++ko)
                mmask |= (ov[ko] == c) ? (1u << ko) : 0u;
            const bool fnd = (mmask != 0u) && (c != 0);
            const int  idx = fnd ? (__ffs(mmask) - 1) : 0;
            const int  gl  = row * 16 + idx;

            // oracle targets are exactly {0,1}; select-form BCE is exact
            const bool tfb = fnd && (((const float*)(sb + OFF_OFIRE))[gl] != 0.0f);
            const bool tvb = fnd && (((const float*)(sb + OFF_OVLD))[gl] != 0.0f);
            const int  ct  = fnd ? ((const int*)(sb + OFF_OCAN))[gl] : 0;

            float p = fminf(fmaxf(th, EPS_F), 1.0f - EPS_F);
            fire_s -= __logf(tfb ? p : 1.0f - p);

            float q = fminf(fmaxf(vv, EPS_F), 1.0f - EPS_F);
            val_s -= __logf(tvb ? q : 1.0f - q);

            if (ct > 0) {
                const float* lp = (const float*)(sb + OFF_CLOG) + (size_t)tid * 3;
                float x0 = lp[0], x1 = lp[1], x2 = lp[2];
                float mx = fmaxf(x0, fmaxf(x1, x2));
                float s2 = __expf(x0 - mx) + __expf(x1 - mx) + __expf(x2 - mx);
                int tgt = ct - 1;
                tgt = tgt < 0 ? 0 : (tgt > 2 ? 2 : tgt);
                float xt = (tgt == 0) ? x0 : ((tgt == 1) ? x1 : x2);
                can_s += mx + __logf(s2) - xt;
                has_s += 1.0f;
            }
        }

        // write-head BCE-with-logits: one per row
        if (k == 0) {
            float wx = ((const float*)(sb + OFF_WSC))[row];
            float wy = ((const float*)(sb + OFF_OSW))[row];
            w_s += fmaxf(wx, 0.0f) - wx * wy + __logf(1.0f + __expf(-fabsf(wx)));
        }

        // warp-granular release of buffer s: one arrive per warp (16 total)
        __syncwarp();
        if ((tid & 31) == 0) mbar_arrive(ebase + (uint32_t)s * 8);

        // producer (tid 0): wait until all 16 warps released buffer s, then refill
        if (tid == 0 && j + NSTAGE < count) {
            mbar_wait(ebase + (uint32_t)s * 8, par);
            stage_tma(j + NSTAGE);
        }
    }

    // ---- Deterministic block reduction of 6 float accumulators ----
    __shared__ float sm[16][6];
    __syncthreads();
    {
        float vals[6] = {fire_s, m_s, val_s, can_s, has_s, w_s};
#pragma unroll
        for (int jj = 0; jj < 6; ++jj) vals[jj] = warp_sum_f(vals[jj]);
        const int wid = tid >> 5, lid = tid & 31;
        if (lid == 0) {
#pragma unroll
            for (int jj = 0; jj < 6; ++jj) sm[wid][jj] = vals[jj];
        }
        __syncthreads();
        if (wid == 0) {
#pragma unroll
            for (int jj = 0; jj < 6; ++jj) {
                float v = (lid < NWARP) ? sm[lid][jj] : 0.0f;
                v = warp_sum_f(v);
                if (lid == 0) g_part[jj * NBLK + blockIdx.x] = v;
            }
        }
    }

    // ---- Last-block finalize ----
    __shared__ int s_last;
    if (tid == 0) {
        __threadfence();
        unsigned int t = atomicAdd(&g_sem, 1u);
        s_last = (t == NBLK - 1) ? 1 : 0;
    }
    __syncthreads();
    if (!s_last) return;

    __shared__ double smd[16];
    double tot[6];
#pragma unroll
    for (int jj = 0; jj < 6; ++jj) {
        double v = 0.0;
        for (int i = tid; i < NBLK; i += NTHR)
            v += (double)__ldcg(&g_part[jj * NBLK + i]);
        v = warp_sum_d(v);
        const int wid = tid >> 5, lid = tid & 31;
        if (lid == 0) smd[wid] = v;
        __syncthreads();
        double r = 0.0;
        if (wid == 0) {
            r = (lid < NWARP) ? smd[lid] : 0.0;
            r = warp_sum_d(r);
        }
        tot[jj] = r;
        __syncthreads();
    }
    if (tid == 0) {
        double n     = fmax(tot[1], 1.0);
        double fire  = tot[0] / n;
        double canc  = (tot[4] > 0.0) ? tot[3] / fmax(tot[4], 1.0) : 0.0;
        double valid = 0.5 * tot[2] / n;
        double wr    = 0.5 * tot[5] / (double)BT_ROWS;
        out[0] = (float)fire;
        out[1] = (float)canc;
        out[2] = (float)valid;
        out[3] = (float)wr;
        out[4] = (float)(fire + canc + valid + wr);
        g_sem = 0;
    }
}

extern "C" void kernel_launch(void* const* d_in, const int* in_sizes, int n_in,
                              void* d_out, int out_size)
{
    (void)in_sizes; (void)n_in; (void)out_size;
    cudaFuncSetAttribute(lifecycle_fused,
                         cudaFuncAttributeMaxDynamicSharedMemorySize, SMEM_TOTAL);
    lifecycle_fused<<<NBLK, NTHR, SMEM_TOTAL>>>(
        (const float*)d_in[0],          // trigger_hazard
        (const float*)d_in[1],          // validity
        (const float*)d_in[2],          // cancel_logits
        (const float*)d_in[3],          // write_score
        d_in[4],                        // live_mask (dtype auto-detected)
        (const int*)d_in[5],            // contract_id
        (const float*)d_in[6],          // oracle_fire
        (const int*)d_in[7],            // oracle_cancel
        (const float*)d_in[8],          // oracle_valid
        (const float*)d_in[9],          // oracle_should_write
        (const int*)d_in[10],           // oracle_contract_id
        (float*)d_out);
}

// round 17
// speedup vs baseline: 1.1144x; 1.1090x over previous
#include <cuda_runtime.h>
#include <math.h>
#include <cstdint>

// Problem constants (fixed by reference: B=32, T=8192, K=16)
#define BT_ROWS   (32 * 8192)
#define KDIM      16
#define ELEMS     (BT_ROWS * KDIM)       // 4194304
#define NTHR      512
#define NWARP     (NTHR / 32)
#define TILE      512                    // elements per stage
#define NTILES    (ELEMS / TILE)         // 8192
#define NBLK      456                    // 152 SMs x 3 CTAs -> single wave
#define NSTAGE    3
#define EPS_F     1e-7f
#define FULLMASK  0xffffffffu

// ---- Stage layout in shared memory (bytes), TILE=512; everything staged ----
#define OFF_CID    0                     // 2 KB each
#define OFF_OCID   2048
#define OFF_TRIG   4096
#define OFF_VLD    6144
#define OFF_OFIRE  8192
#define OFF_OVLD   10240
#define OFF_OCAN   12288
#define OFF_CLOG   14336                 // 6 KB
#define OFF_LIVE   20480                 // up to 2 KB
#define OFF_WSC    22528                 // 128 B (32 rows)
#define OFF_OSW    22656                 // 128 B
#define STAGE_BYTES 22784
#define OFF_TBL    (NSTAGE * STAGE_BYTES)        // 4 KB match table (shared across stages)
#define SMEM_TOTAL  (NSTAGE * STAGE_BYTES + 4096) // 72448 -> 3 CTAs/SM

// Per-block partial sums: [6][NBLK]
__device__ float g_part[6 * NBLK];
__device__ unsigned int g_sem;

__device__ __forceinline__ float warp_sum_f(float v) {
#pragma unroll
    for (int o = 16; o > 0; o >>= 1) v += __shfl_down_sync(FULLMASK, v, o);
    return v;
}
__device__ __forceinline__ double warp_sum_d(double v) {
#pragma unroll
    for (int o = 16; o > 0; o >>= 1) v += __shfl_down_sync(FULLMASK, v, o);
    return v;
}

// ---- TMA 1D bulk copy + mbarrier helpers ----
__device__ __forceinline__ void tma_bulk(uint32_t dst, const void* src,
                                         uint32_t size, uint32_t mbar) {
    asm volatile(
        "cp.async.bulk.shared::cta.global.mbarrier::complete_tx::bytes "
        "[%0], [%1], %2, [%3];"
        :: "r"(dst), "l"(src), "r"(size), "r"(mbar) : "memory");
}
__device__ __forceinline__ void mbar_init(uint32_t mbar, uint32_t count) {
    asm volatile("mbarrier.init.shared.b64 [%0], %1;" :: "r"(mbar), "r"(count) : "memory");
}
__device__ __forceinline__ void mbar_expect_tx(uint32_t mbar, uint32_t bytes) {
    asm volatile("mbarrier.arrive.expect_tx.shared.b64 _, [%0], %1;"
                 :: "r"(mbar), "r"(bytes) : "memory");
}
__device__ __forceinline__ void mbar_wait(uint32_t mbar, uint32_t parity) {
    asm volatile(
        "{\n\t"
        ".reg .pred P;\n\t"
        "LAB_WAIT_%=:\n\t"
        "mbarrier.try_wait.parity.acquire.cta.shared::cta.b64 P, [%0], %1, 0x989680;\n\t"
        "@P bra LAB_DONE_%=;\n\t"
        "bra LAB_WAIT_%=;\n\t"
        "LAB_DONE_%=:\n\t"
        "}"
        :: "r"(mbar), "r"(parity) : "memory");
}

__global__ __launch_bounds__(NTHR, 3)
void lifecycle_fused(const float* __restrict__ trig,
                     const float* __restrict__ vld,
                     const float* __restrict__ clog,
                     const float* __restrict__ wsc,
                     const void*  __restrict__ live_raw,
                     const int*   __restrict__ cid,
                     const float* __restrict__ ofire,
                     const int*   __restrict__ ocan,
                     const float* __restrict__ ovld,
                     const float* __restrict__ osw,
                     const int*   __restrict__ ocid,
                     float* __restrict__ out)
{
    extern __shared__ char smem[];
    __shared__ __align__(8) unsigned long long s_full[NSTAGE];

    // ---- live_mask dtype sniff (same 64 words for every block; L2 broadcast) ----
    __shared__ unsigned int s_or, s_f32;
    __shared__ int s_mode;
    if (threadIdx.x == 0) { s_or = 0u; s_f32 = 0u; }
    __syncthreads();
    if (threadIdx.x < 64) {
        unsigned int x = ((const unsigned int*)live_raw)[threadIdx.x];
        unsigned int f = (x == 0x3F800000u) ? 1u : 0u;
        unsigned int a = f ? 0u : x;
#pragma unroll
        for (int o = 16; o > 0; o >>= 1) {
            a |= __shfl_down_sync(FULLMASK, a, o);
            f |= __shfl_down_sync(FULLMASK, f, o);
        }
        if ((threadIdx.x & 31) == 0) { atomicOr(&s_or, a); atomicOr(&s_f32, f); }
    }
    __syncthreads();
    if (threadIdx.x == 0) s_mode = s_f32 ? 2 : ((s_or & ~1u) ? 0 : 1);
    __syncthreads();
    const int mode = s_mode;                    // 0=u8, 1=i32, 2=f32

    const int tid = threadIdx.x;
    const int bid = blockIdx.x;
    const int count = (NTILES - bid + NBLK - 1) / NBLK;   // tiles for this block

    const uint32_t sbase = (uint32_t)__cvta_generic_to_shared(smem);
    const uint32_t fbase = (uint32_t)__cvta_generic_to_shared(s_full);
    const uint32_t live_sz = (mode == 0) ? 512u : 2048u;
    const uint32_t tx_bytes = 7*2048u + 6144u + live_sz + 128u + 128u;

    unsigned int* s_tbl = (unsigned int*)(smem + OFF_TBL);   // [32 rows][32 ids]

    // ---- mbarrier init ----
    if (tid == 0) {
#pragma unroll
        for (int s = 0; s < NSTAGE; ++s) mbar_init(fbase + s*8, 1);
    }
    __syncthreads();

    // ---- tile stage via TMA bulk (single thread issues 11 descriptors) ----
    auto stage_tma = [&](int j) {   // j = local tile ordinal; caller: tid==0 only
        const int t = bid + j * NBLK;
        const size_t eb = (size_t)t * TILE;
        const int s = j % NSTAGE;
        const uint32_t sb = sbase + (uint32_t)s * STAGE_BYTES;
        const uint32_t mb = fbase + (uint32_t)s * 8;
        mbar_expect_tx(mb, tx_bytes);
        tma_bulk(sb + OFF_CID,   (const char*)cid   + eb*4, 2048, mb);
        tma_bulk(sb + OFF_OCID,  (const char*)ocid  + eb*4, 2048, mb);
        tma_bulk(sb + OFF_TRIG,  (const char*)trig  + eb*4, 2048, mb);
        tma_bulk(sb + OFF_VLD,   (const char*)vld   + eb*4, 2048, mb);
        tma_bulk(sb + OFF_OFIRE, (const char*)ofire + eb*4, 2048, mb);
        tma_bulk(sb + OFF_OVLD,  (const char*)ovld  + eb*4, 2048, mb);
        tma_bulk(sb + OFF_OCAN,  (const char*)ocan  + eb*4, 2048, mb);
        tma_bulk(sb + OFF_CLOG,  (const char*)clog  + eb*12, 6144, mb);
        if (mode == 0) tma_bulk(sb + OFF_LIVE, (const char*)live_raw + eb,   512,  mb);
        else           tma_bulk(sb + OFF_LIVE, (const char*)live_raw + eb*4, 2048, mb);
        tma_bulk(sb + OFF_WSC, (const char*)wsc + (eb >> 4)*4, 128, mb);
        tma_bulk(sb + OFF_OSW, (const char*)osw + (eb >> 4)*4, 128, mb);
    };

    float fire_s = 0.f, m_s = 0.f, val_s = 0.f, can_s = 0.f, has_s = 0.f, w_s = 0.f;

    const int k   = tid & 15;   // element within row
    const int row = tid >> 4;   // local row (32 rows per tile)

    // ---- prologue: fill all 3 stages ----
    if (tid == 0) { stage_tma(0); stage_tma(1); stage_tma(2); }

#pragma unroll 1
    for (int j = 0; j < count; ++j) {
        const int s = j % NSTAGE;
        mbar_wait(fbase + (uint32_t)s * 8, (uint32_t)((j / NSTAGE) & 1));

        const char* sb = smem + s * STAGE_BYTES;

        // ---- build per-row first-match table: tbl[row][v] = min ko with ocid==v ----
        s_tbl[tid] = 0xFFFFFFFFu;            // 1024 entries, 2 per thread
        s_tbl[tid + NTHR] = 0xFFFFFFFFu;
        __syncthreads();
        const int oc_own = ((const int*)(sb + OFF_OCID))[tid];
        atomicMin(&s_tbl[row * 32 + (oc_own & 31)], (unsigned int)k);
        __syncthreads();

        const int   c  = ((const int*)(sb + OFF_CID))[tid];
        const float th = ((const float*)(sb + OFF_TRIG))[tid];
        const float vv = ((const float*)(sb + OFF_VLD))[tid];

        bool lm;
        if (mode == 0)      lm = ((const unsigned char*)(sb + OFF_LIVE))[tid] != 0;
        else if (mode == 1) lm = ((const int*)(sb + OFF_LIVE))[tid] != 0;
        else                lm = ((const float*)(sb + OFF_LIVE))[tid] != 0.0f;

        if (lm) {
            m_s += 1.0f;

            // O(1) first-match lookup (contract ids bounded to [0,32) by the reference)
            const unsigned int idx = s_tbl[row * 32 + (c & 31)];
            const bool fnd = (c != 0) && (idx < 16u);
            const int  gl  = row * 16 + (fnd ? (int)idx : 0);

            // oracle targets are exactly {0,1}; select-form BCE is exact
            const bool tfb = fnd && (((const float*)(sb + OFF_OFIRE))[gl] != 0.0f);
            const bool tvb = fnd && (((const float*)(sb + OFF_OVLD))[gl] != 0.0f);
            const int  ct  = fnd ? ((const int*)(sb + OFF_OCAN))[gl] : 0;

            float p = fminf(fmaxf(th, EPS_F), 1.0f - EPS_F);
            fire_s -= __logf(tfb ? p : 1.0f - p);

            float q = fminf(fmaxf(vv, EPS_F), 1.0f - EPS_F);
            val_s -= __logf(tvb ? q : 1.0f - q);

            if (ct > 0) {
                const float* lp = (const float*)(sb + OFF_CLOG) + (size_t)tid * 3;
                float x0 = lp[0], x1 = lp[1], x2 = lp[2];
                float mx = fmaxf(x0, fmaxf(x1, x2));
                float s2 = __expf(x0 - mx) + __expf(x1 - mx) + __expf(x2 - mx);
                int tgt = ct - 1;
                tgt = tgt < 0 ? 0 : (tgt > 2 ? 2 : tgt);
                float xt = (tgt == 0) ? x0 : ((tgt == 1) ? x1 : x2);
                can_s += mx + __logf(s2) - xt;
                has_s += 1.0f;
            }
        }

        // write-head BCE-with-logits: one per row
        if (k == 0) {
            float wx = ((const float*)(sb + OFF_WSC))[row];
            float wy = ((const float*)(sb + OFF_OSW))[row];
            w_s += fmaxf(wx, 0.0f) - wx * wy + __logf(1.0f + __expf(-fabsf(wx)));
        }

        __syncthreads();        // everyone done reading buffer s (and table)
        // refill the buffer just consumed
        if (tid == 0 && j + NSTAGE < count) stage_tma(j + NSTAGE);
    }

    // ---- Deterministic block reduction of 6 float accumulators ----
    __shared__ float sm[16][6];
    {
        float vals[6] = {fire_s, m_s, val_s, can_s, has_s, w_s};
#pragma unroll
        for (int jj = 0; jj < 6; ++jj) vals[jj] = warp_sum_f(vals[jj]);
        const int wid = tid >> 5, lid = tid & 31;
        if (lid == 0) {
#pragma unroll
            for (int jj = 0; jj < 6; ++jj) sm[wid][jj] = vals[jj];
        }
        __syncthreads();
        if (wid == 0) {
#pragma unroll
            for (int jj = 0; jj < 6; ++jj) {
                float v = (lid < NWARP) ? sm[lid][jj] : 0.0f;
                v = warp_sum_f(v);
                if (lid == 0) g_part[jj * NBLK + blockIdx.x] = v;
            }
        }
    }

    // ---- Last-block finalize ----
    __shared__ int s_last;
    if (tid == 0) {
        __threadfence();
        unsigned int t = atomicAdd(&g_sem, 1u);
        s_last = (t == NBLK - 1) ? 1 : 0;
    }
    __syncthreads();
    if (!s_last) return;

    __shared__ double smd[16];
    double tot[6];
#pragma unroll
    for (int jj = 0; jj < 6; ++jj) {
        double v = 0.0;
        for (int i = tid; i < NBLK; i += NTHR)
            v += (double)__ldcg(&g_part[jj * NBLK + i]);
        v = warp_sum_d(v);
        const int wid = tid >> 5, lid = tid & 31;
        if (lid == 0) smd[wid] = v;
        __syncthreads();
        double r = 0.0;
        if (wid == 0) {
            r = (lid < NWARP) ? smd[lid] : 0.0;
            r = warp_sum_d(r);
        }
        tot[jj] = r;
        __syncthreads();
    }
    if (tid == 0) {
        double n     = fmax(tot[1], 1.0);
        double fire  = tot[0] / n;
        double canc  = (tot[4] > 0.0) ? tot[3] / fmax(tot[4], 1.0) : 0.0;
        double valid = 0.5 * tot[2] / n;
        double wr    = 0.5 * tot[5] / (double)BT_ROWS;
        out[0] = (float)fire;
        out[1] = (float)canc;
        out[2] = (float)valid;
        out[3] = (float)wr;
        out[4] = (float)(fire + canc + valid + wr);
        g_sem = 0;
    }
}

extern "C" void kernel_launch(void* const* d_in, const int* in_sizes, int n_in,
                              void* d_out, int out_size)
{
    (void)in_sizes; (void)n_in; (void)out_size;
    cudaFuncSetAttribute(lifecycle_fused,
                         cudaFuncAttributeMaxDynamicSharedMemorySize, SMEM_TOTAL);
    lifecycle_fused<<<NBLK, NTHR, SMEM_TOTAL>>>(
        (const float*)d_in[0],          // trigger_hazard
        (const float*)d_in[1],          // validity
        (const float*)d_in[2],          // cancel_logits
        (const float*)d_in[3],          // write_score
        d_in[4],                        // live_mask (dtype auto-detected)
        (const int*)d_in[5],            // contract_id
        (const float*)d_in[6],          // oracle_fire
        (const int*)d_in[7],            // oracle_cancel
        (const float*)d_in[8],          // oracle_valid
        (const float*)d_in[9],          // oracle_should_write
        (const int*)d_in[10],           // oracle_contract_id
        (float*)d_out);
}